// round 15
// baseline (speedup 1.0000x reference)
#include <cuda_runtime.h>
#include <cuda_bf16.h>
#include <math.h>

#define VSZ 21128
#define HSZ 256
#define KT  21
#define KP  24
#define BB  64
#define TT  512
#define G4  1024
#define NCTA_LSTM 128u
#define BT  (BB*TT)

// ---------------- device scratch ----------------
__device__ float g_pre[2][VSZ][G4];          // emb@wih^T + b per dir
__device__ float g_hbuf[2][2][HSZ][BB];      // [dir][parity][unit][batch]
__device__ float g_hall[2][TT][HSZ][BB];     // [dir][t][unit][batch]
__device__ float g_em[TT][BB][KP];           // emissions [t][b][k] (padded 24)
__device__ float g_nll[BB];
__device__ unsigned g_count;
__device__ unsigned g_sense;

// ---------------- Kernel 1: vocab pre-projection GEMM (double-buffered, proven) ----------------
__global__ void __launch_bounds__(256) gemm_pre_kernel(
    const float* __restrict__ emb,
    const float* __restrict__ wih_f, const float* __restrict__ b_f,
    const float* __restrict__ wih_b, const float* __restrict__ b_b)
{
    __shared__ float As[2][16][128];
    __shared__ float Bs[2][16][128];

    const int dir = blockIdx.z;
    const float* __restrict__ W    = dir ? wih_b : wih_f;
    const float* __restrict__ bias = dir ? b_b   : b_f;
    const int vbase = blockIdx.y * 128;
    const int gbase = blockIdx.x * 128;
    const int tid = threadIdx.x;
    const int tx = tid & 15;
    const int ty = tid >> 4;

    int rowj[2], c4j[2], vj[2], gj[2];
#pragma unroll
    for (int j = 0; j < 2; ++j) {
        int f = tid * 2 + j;
        rowj[j] = f >> 2;
        c4j[j]  = f & 3;
        int v = vbase + rowj[j]; if (v >= VSZ) v = VSZ - 1;
        vj[j] = v;
        gj[j] = gbase + rowj[j];
    }

    float acc[8][8];
#pragma unroll
    for (int i = 0; i < 8; ++i)
#pragma unroll
        for (int j = 0; j < 8; ++j) acc[i][j] = 0.f;

    float4 ar[2], br[2];

#pragma unroll
    for (int j = 0; j < 2; ++j) {
        ar[j] = *(const float4*)&emb[(size_t)vj[j] * 256 + c4j[j] * 4];
        br[j] = *(const float4*)&W[(size_t)gj[j] * 256 + c4j[j] * 4];
    }
#pragma unroll
    for (int j = 0; j < 2; ++j) {
        int r = rowj[j], c4 = c4j[j];
        As[0][c4*4+0][r] = ar[j].x; As[0][c4*4+1][r] = ar[j].y;
        As[0][c4*4+2][r] = ar[j].z; As[0][c4*4+3][r] = ar[j].w;
        Bs[0][c4*4+0][r] = br[j].x; Bs[0][c4*4+1][r] = br[j].y;
        Bs[0][c4*4+2][r] = br[j].z; Bs[0][c4*4+3][r] = br[j].w;
    }
    __syncthreads();

    for (int c = 0; c < 16; ++c) {
        const int buf = c & 1;
        if (c < 15) {
            const int k0 = (c + 1) * 16;
#pragma unroll
            for (int j = 0; j < 2; ++j) {
                ar[j] = *(const float4*)&emb[(size_t)vj[j] * 256 + k0 + c4j[j] * 4];
                br[j] = *(const float4*)&W[(size_t)gj[j] * 256 + k0 + c4j[j] * 4];
            }
        }
#pragma unroll
        for (int k = 0; k < 16; ++k) {
            float4 a0 = *(const float4*)&As[buf][k][ty*8];
            float4 a1 = *(const float4*)&As[buf][k][ty*8+4];
            float4 c0 = *(const float4*)&Bs[buf][k][tx*8];
            float4 c1 = *(const float4*)&Bs[buf][k][tx*8+4];
            float am[8] = {a0.x,a0.y,a0.z,a0.w,a1.x,a1.y,a1.z,a1.w};
            float bm[8] = {c0.x,c0.y,c0.z,c0.w,c1.x,c1.y,c1.z,c1.w};
#pragma unroll
            for (int i = 0; i < 8; ++i)
#pragma unroll
                for (int j = 0; j < 8; ++j)
                    acc[i][j] = fmaf(am[i], bm[j], acc[i][j]);
        }
        if (c < 15) {
            __syncthreads();
            const int nb = (c + 1) & 1;
#pragma unroll
            for (int j = 0; j < 2; ++j) {
                int r = rowj[j], c4 = c4j[j];
                As[nb][c4*4+0][r] = ar[j].x; As[nb][c4*4+1][r] = ar[j].y;
                As[nb][c4*4+2][r] = ar[j].z; As[nb][c4*4+3][r] = ar[j].w;
                Bs[nb][c4*4+0][r] = br[j].x; Bs[nb][c4*4+1][r] = br[j].y;
                Bs[nb][c4*4+2][r] = br[j].z; Bs[nb][c4*4+3][r] = br[j].w;
            }
            __syncthreads();
        }
    }

#pragma unroll
    for (int i = 0; i < 8; ++i) {
        int v = vbase + ty * 8 + i;
        if (v < VSZ) {
#pragma unroll
            for (int j = 0; j < 8; j += 4) {
                int g = gbase + tx * 8 + j;
                float4 o;
                o.x = acc[i][j+0] + bias[g+0];
                o.y = acc[i][j+1] + bias[g+1];
                o.z = acc[i][j+2] + bias[g+2];
                o.w = acc[i][j+3] + bias[g+3];
                *(float4*)&g_pre[dir][v][g] = o;
            }
        }
    }
}

// ---------------- barrier state init ----------------
__global__ void barrier_init_kernel() { g_count = 0u; g_sense = 0u; }

// ---------------- Kernel 2: persistent biLSTM (R12 winner + latency hiding) ----------------
__device__ __forceinline__ float sigf(float x) { return 1.f / (1.f + __expf(-x)); }

// Global CG-style grid barrier (R12 winner): fence only in elected thread.
__device__ __forceinline__ void grid_barrier(int tid, unsigned target) {
    __syncthreads();               // all threads' h stores happen-before tid0's fence
    if (tid == 0) {
        __threadfence();           // publish (cumulative over the block)
        unsigned arr = atomicAdd(&g_count, 1u);
        if (arr == NCTA_LSTM - 1u) {
            atomicExch(&g_count, 0u);
            __threadfence();
            atomicExch(&g_sense, target);
        } else {
            while (*(volatile unsigned*)&g_sense < target) { }
        }
    }
    __syncthreads();
}

__global__ void __launch_bounds__(256) lstm_kernel(
    const int* __restrict__ x,
    const float* __restrict__ whh_f, const float* __restrict__ whh_b)
{
    extern __shared__ float sm[];
    float* wsm = sm;          // [256][16] : wsm[k*16 + u*4 + q]
    float* hsm = sm + 4096;   // [256][64] : hsm[k*64 + b]

    const int tid = threadIdx.x;
    const int bx  = blockIdx.x;
    const int dir = bx >> 6;
    const int u0  = (bx & 63) * 4;
    const int ul  = tid >> 6;
    const int b   = tid & 63;

    const float* __restrict__ whh = dir ? whh_b : whh_f;

    for (int i = tid; i < 4096; i += 256) {
        int r = i >> 8, k = i & 255;
        int u = r >> 2, q = r & 3;
        wsm[k * 16 + u * 4 + q] = whh[(size_t)(q * 256 + u0 + u) * 256 + k];
    }
    g_hbuf[dir][0][u0 + ul][b] = 0.f;

    const float* __restrict__ preb = &g_pre[dir][0][0];

    // t=0 prefetch of input projection (hidden behind barrier slack)
    int tok0 = __ldg(&x[b * TT + (dir ? TT - 1 : 0)]);
    const float* pr0 = preb + (size_t)tok0 * G4 + u0 + ul;
    float p0 = __ldg(pr0), p1 = __ldg(pr0 + 256), p2 = __ldg(pr0 + 512), p3 = __ldg(pr0 + 768);

    grid_barrier(tid, 1u);

    float c = 0.f;

    for (int t = 0; t < TT; ++t) {
        // stage the full h(t) into registers (MLP=16), then split-fill hsm
        const float4* hg = (const float4*)&g_hbuf[dir][t & 1][0][0];
        float4 st[16];
#pragma unroll
        for (int i = 0; i < 16; ++i) st[i] = __ldcg(&hg[i * 256 + tid]);

        float4* hs4 = (float4*)hsm;
#pragma unroll
        for (int i = 0; i < 8; ++i) hs4[i * 256 + tid] = st[i];   // covers k < 128
        __syncthreads();

        float a0 = p0, a1 = p1, a2 = p2, a3 = p3;

#pragma unroll 8
        for (int k = 0; k < 128; ++k) {
            float4 w = *(const float4*)&wsm[k * 16 + ul * 4];
            float hv = hsm[k * 64 + b];
            a0 = fmaf(w.x, hv, a0);
            a1 = fmaf(w.y, hv, a1);
            a2 = fmaf(w.z, hv, a2);
            a3 = fmaf(w.w, hv, a3);
        }

#pragma unroll
        for (int i = 8; i < 16; ++i) hs4[i * 256 + tid] = st[i];  // covers k >= 128
        __syncthreads();

#pragma unroll 8
        for (int k = 128; k < 256; ++k) {
            float4 w = *(const float4*)&wsm[k * 16 + ul * 4];
            float hv = hsm[k * 64 + b];
            a0 = fmaf(w.x, hv, a0);
            a1 = fmaf(w.y, hv, a1);
            a2 = fmaf(w.z, hv, a2);
            a3 = fmaf(w.w, hv, a3);
        }

        float ig = sigf(a0), fg = sigf(a1), gg = tanhf(a2), og = sigf(a3);
        c = fg * c + ig * gg;
        float h = og * tanhf(c);

        const int tpos = dir ? (TT - 1 - t) : t;
        g_hbuf[dir][(t + 1) & 1][u0 + ul][b] = h;
        g_hall[dir][tpos][u0 + ul][b] = h;

        // prefetch next step's projection before the barrier spin
        if (t + 1 < TT) {
            int tpn = dir ? (TT - 2 - t) : (t + 1);
            int tok = __ldg(&x[b * TT + tpn]);
            const float* pr = preb + (size_t)tok * G4 + u0 + ul;
            p0 = __ldg(pr); p1 = __ldg(pr + 256); p2 = __ldg(pr + 512); p3 = __ldg(pr + 768);
        }

        grid_barrier(tid, (unsigned)(t + 2));  // also protects hsm reuse
    }
}

// ---------------- Kernel 3: emissions (proven, 54us) ----------------
__global__ void __launch_bounds__(384) emission_kernel(
    const float* __restrict__ wc, const float* __restrict__ bc)
{
    extern __shared__ float wcs[];   // [512][24]

    const int t = blockIdx.x;
    const int tid = threadIdx.x;

    for (int i = tid; i < KP * 512; i += 384) {
        int k = i / 512, u = i - k * 512;
        wcs[u * KP + k] = (k < KT) ? wc[k * 512 + u] : 0.f;
    }
    __syncthreads();

    const int kk = tid >> 6;   // 0..5
    const int b  = tid & 63;

    float r0 = 0.f, r1 = 0.f, r2 = 0.f, r3 = 0.f;
    const float* h0 = &g_hall[0][t][0][0] + b;
    const float* h1 = &g_hall[1][t][0][0] + b;
#pragma unroll 8
    for (int u = 0; u < 256; ++u) {
        float4 w = *(const float4*)&wcs[u * KP + kk * 4];
        float hv = __ldcg(h0 + u * 64);
        r0 = fmaf(w.x, hv, r0);
        r1 = fmaf(w.y, hv, r1);
        r2 = fmaf(w.z, hv, r2);
        r3 = fmaf(w.w, hv, r3);
    }
#pragma unroll 8
    for (int u = 0; u < 256; ++u) {
        float4 w = *(const float4*)&wcs[(u + 256) * KP + kk * 4];
        float hv = __ldcg(h1 + u * 64);
        r0 = fmaf(w.x, hv, r0);
        r1 = fmaf(w.y, hv, r1);
        r2 = fmaf(w.z, hv, r2);
        r3 = fmaf(w.w, hv, r3);
    }

    const int k0 = kk * 4;
    float4 o;
    o.x = r0 + __ldg(&bc[min(k0 + 0, KT - 1)]);
    o.y = r1 + __ldg(&bc[min(k0 + 1, KT - 1)]);
    o.z = r2 + __ldg(&bc[min(k0 + 2, KT - 1)]);
    o.w = r3 + __ldg(&bc[min(k0 + 3, KT - 1)]);
    *(float4*)&g_em[t][b][k0] = o;
}

// ---------------- Kernel 4: CRF — warp0 viterbi, warp1 forward (proven) ----------------
__global__ void __launch_bounds__(64) crf_kernel(
    const int* __restrict__ y,
    const float* __restrict__ startv, const float* __restrict__ endv,
    const float* __restrict__ trans, float* __restrict__ out)
{
    __shared__ float tr[KT * KT];
    __shared__ float sv[32];
    __shared__ float sa[32];
    __shared__ unsigned char bp[TT][KT];

    const int b = blockIdx.x;
    const int tid = threadIdx.x;
    const int w = tid >> 5;
    const int lane = tid & 31;
    const bool act = lane < KT;

    for (int i = tid; i < KT * KT; i += 64) tr[i] = trans[i];
    __syncthreads();

    if (w == 0) {
        if (act) sv[lane] = startv[lane] + g_em[0][b][lane];
        __syncwarp();
        float e_next = act ? g_em[1][b][lane] : 0.f;
        for (int t = 1; t < TT; ++t) {
            float e = e_next;
            if (t + 1 < TT) e_next = act ? g_em[t + 1][b][lane] : 0.f;
            float best = -1e30f; int bi = 0;
#pragma unroll
            for (int i = 0; i < KT; ++i) {
                float v = sv[i] + tr[i * KT + lane];
                if (v > best) { best = v; bi = i; }
            }
            __syncwarp();
            if (act) { sv[lane] = best + e; bp[t][lane] = (unsigned char)bi; }
            __syncwarp();
        }
        float fin = act ? sv[lane] + endv[lane] : -1e30f;
        int idx = act ? lane : 0;
#pragma unroll
        for (int o = 16; o; o >>= 1) {
            float of = __shfl_down_sync(0xFFFFFFFFu, fin, o);
            int   oi = __shfl_down_sync(0xFFFFFFFFu, idx, o);
            if (of > fin) { fin = of; idx = oi; }
        }
        idx = __shfl_sync(0xFFFFFFFFu, idx, 0);
        if (lane == 0) {
            int tag = idx;
            out[b * TT + TT - 1] = (float)tag;
            for (int t = TT - 1; t >= 1; --t) {
                tag = bp[t][tag];
                out[b * TT + t - 1] = (float)tag;
            }
        }
    } else {
        if (act) sa[lane] = startv[lane] + g_em[0][b][lane];
        __syncwarp();
        float e_next = act ? g_em[1][b][lane] : 0.f;
        for (int t = 1; t < TT; ++t) {
            float e = e_next;
            if (t + 1 < TT) e_next = act ? g_em[t + 1][b][lane] : 0.f;
            float amax = -1e30f;
#pragma unroll
            for (int i = 0; i < KT; ++i)
                amax = fmaxf(amax, sa[i] + tr[i * KT + lane]);
            float s = 0.f;
#pragma unroll
            for (int i = 0; i < KT; ++i)
                s += __expf(sa[i] + tr[i * KT + lane] - amax);
            float na = amax + __logf(s) + e;
            __syncwarp();
            if (act) sa[lane] = na;
            __syncwarp();
        }
        float fin = act ? sa[lane] + endv[lane] : -1e30f;
        float m = fin;
#pragma unroll
        for (int o = 16; o; o >>= 1) m = fmaxf(m, __shfl_xor_sync(0xFFFFFFFFu, m, o));
        float s = act ? __expf(fin - m) : 0.f;
#pragma unroll
        for (int o = 16; o; o >>= 1) s += __shfl_xor_sync(0xFFFFFFFFu, s, o);
        float z = m + __logf(s);

        float part = 0.f;
        for (int t = 1 + lane; t < TT; t += 32) {
            int yp = y[b * TT + t - 1], yc = y[b * TT + t];
            part += tr[yp * KT + yc] + g_em[t][b][yc];
        }
#pragma unroll
        for (int o = 16; o; o >>= 1) part += __shfl_down_sync(0xFFFFFFFFu, part, o);
        if (lane == 0) {
            int y0 = y[b * TT];
            int yl = y[b * TT + TT - 1];
            float num = startv[y0] + g_em[0][b][y0] + part + endv[yl];
            g_nll[b] = num - z;
        }
    }
}

// ---------------- Kernel 5: finalize loss ----------------
__global__ void __launch_bounds__(64) finalize_kernel(float* out, int out_size)
{
    __shared__ float s[64];
    s[threadIdx.x] = g_nll[threadIdx.x];
    __syncthreads();
    if (threadIdx.x == 0) {
        float t = 0.f;
        for (int i = 0; i < 64; ++i) t += s[i];
        float loss = t / 64.f;
        if (out_size > BT) out[BT] = loss;
        if (out_size - 1 > BT) out[out_size - 1] = loss;
    }
}

// ---------------- launch ----------------
extern "C" void kernel_launch(void* const* d_in, const int* in_sizes, int n_in,
                              void* d_out, int out_size)
{
    const int*   x      = (const int*)d_in[0];
    const int*   y      = (const int*)d_in[1];
    const float* emb    = (const float*)d_in[3];
    const float* wih_f  = (const float*)d_in[4];
    const float* whh_f  = (const float*)d_in[5];
    const float* b_f    = (const float*)d_in[6];
    const float* wih_b  = (const float*)d_in[7];
    const float* whh_b  = (const float*)d_in[8];
    const float* b_b    = (const float*)d_in[9];
    const float* wc     = (const float*)d_in[10];
    const float* bc     = (const float*)d_in[11];
    const float* startv = (const float*)d_in[12];
    const float* endv   = (const float*)d_in[13];
    const float* trans  = (const float*)d_in[14];
    float* out = (float*)d_out;

    cudaFuncSetAttribute(lstm_kernel,
        cudaFuncAttributeMaxDynamicSharedMemorySize, 81920);
    cudaFuncSetAttribute(emission_kernel,
        cudaFuncAttributeMaxDynamicSharedMemorySize, 49152);

    gemm_pre_kernel<<<dim3(8, 166, 2), 256>>>(emb, wih_f, b_f, wih_b, b_b);
    barrier_init_kernel<<<1, 1>>>();
    lstm_kernel<<<NCTA_LSTM, 256, 81920>>>(x, whh_f, whh_b);
    emission_kernel<<<TT, 384, 49152>>>(wc, bc);
    crf_kernel<<<BB, 64>>>(y, startv, endv, trans, out);
    finalize_kernel<<<1, 64>>>(out, out_size);
}

// round 16
// speedup vs baseline: 1.0364x; 1.0364x over previous
#include <cuda_runtime.h>
#include <cuda_bf16.h>
#include <math.h>

#define VSZ 21128
#define HSZ 256
#define KT  21
#define KP  24
#define BB  64
#define TT  512
#define G4  1024
#define NCTA_LSTM 128u
#define BT  (BB*TT)

// ---------------- device scratch ----------------
__device__ float g_pre[2][VSZ][G4];          // emb@wih^T + b per dir, layout [v][u][q] (q=gate)
__device__ float g_hbuf[2][2][HSZ][BB];      // [dir][parity][unit][batch]
__device__ float g_hall[2][TT][HSZ][BB];     // [dir][t][unit][batch]
__device__ float g_em[TT][BB][KP];           // emissions [t][b][k] (padded 24)
__device__ float g_nll[BB];
__device__ unsigned g_count;
__device__ unsigned g_sense;

// ---------------- Kernel 1: vocab pre-projection GEMM (double-buffered, proven) ----------------
// Epilogue stores into interleaved [v][u][4] layout (one float4 per unit in the LSTM).
__global__ void __launch_bounds__(256) gemm_pre_kernel(
    const float* __restrict__ emb,
    const float* __restrict__ wih_f, const float* __restrict__ b_f,
    const float* __restrict__ wih_b, const float* __restrict__ b_b)
{
    __shared__ float As[2][16][128];
    __shared__ float Bs[2][16][128];

    const int dir = blockIdx.z;
    const float* __restrict__ W    = dir ? wih_b : wih_f;
    const float* __restrict__ bias = dir ? b_b   : b_f;
    const int vbase = blockIdx.y * 128;
    const int gbase = blockIdx.x * 128;
    const int tid = threadIdx.x;
    const int tx = tid & 15;
    const int ty = tid >> 4;

    int rowj[2], c4j[2], vj[2], gj[2];
#pragma unroll
    for (int j = 0; j < 2; ++j) {
        int f = tid * 2 + j;
        rowj[j] = f >> 2;
        c4j[j]  = f & 3;
        int v = vbase + rowj[j]; if (v >= VSZ) v = VSZ - 1;
        vj[j] = v;
        gj[j] = gbase + rowj[j];
    }

    float acc[8][8];
#pragma unroll
    for (int i = 0; i < 8; ++i)
#pragma unroll
        for (int j = 0; j < 8; ++j) acc[i][j] = 0.f;

    float4 ar[2], br[2];

#pragma unroll
    for (int j = 0; j < 2; ++j) {
        ar[j] = *(const float4*)&emb[(size_t)vj[j] * 256 + c4j[j] * 4];
        br[j] = *(const float4*)&W[(size_t)gj[j] * 256 + c4j[j] * 4];
    }
#pragma unroll
    for (int j = 0; j < 2; ++j) {
        int r = rowj[j], c4 = c4j[j];
        As[0][c4*4+0][r] = ar[j].x; As[0][c4*4+1][r] = ar[j].y;
        As[0][c4*4+2][r] = ar[j].z; As[0][c4*4+3][r] = ar[j].w;
        Bs[0][c4*4+0][r] = br[j].x; Bs[0][c4*4+1][r] = br[j].y;
        Bs[0][c4*4+2][r] = br[j].z; Bs[0][c4*4+3][r] = br[j].w;
    }
    __syncthreads();

    for (int c = 0; c < 16; ++c) {
        const int buf = c & 1;
        if (c < 15) {
            const int k0 = (c + 1) * 16;
#pragma unroll
            for (int j = 0; j < 2; ++j) {
                ar[j] = *(const float4*)&emb[(size_t)vj[j] * 256 + k0 + c4j[j] * 4];
                br[j] = *(const float4*)&W[(size_t)gj[j] * 256 + k0 + c4j[j] * 4];
            }
        }
#pragma unroll
        for (int k = 0; k < 16; ++k) {
            float4 a0 = *(const float4*)&As[buf][k][ty*8];
            float4 a1 = *(const float4*)&As[buf][k][ty*8+4];
            float4 c0 = *(const float4*)&Bs[buf][k][tx*8];
            float4 c1 = *(const float4*)&Bs[buf][k][tx*8+4];
            float am[8] = {a0.x,a0.y,a0.z,a0.w,a1.x,a1.y,a1.z,a1.w};
            float bm[8] = {c0.x,c0.y,c0.z,c0.w,c1.x,c1.y,c1.z,c1.w};
#pragma unroll
            for (int i = 0; i < 8; ++i)
#pragma unroll
                for (int j = 0; j < 8; ++j)
                    acc[i][j] = fmaf(am[i], bm[j], acc[i][j]);
        }
        if (c < 15) {
            __syncthreads();
            const int nb = (c + 1) & 1;
#pragma unroll
            for (int j = 0; j < 2; ++j) {
                int r = rowj[j], c4 = c4j[j];
                As[nb][c4*4+0][r] = ar[j].x; As[nb][c4*4+1][r] = ar[j].y;
                As[nb][c4*4+2][r] = ar[j].z; As[nb][c4*4+3][r] = ar[j].w;
                Bs[nb][c4*4+0][r] = br[j].x; Bs[nb][c4*4+1][r] = br[j].y;
                Bs[nb][c4*4+2][r] = br[j].z; Bs[nb][c4*4+3][r] = br[j].w;
            }
            __syncthreads();
        }
    }

    // epilogue: interleaved store g_pre[v][u*4 + q], q = gate index of this g-block
    const int q  = gbase >> 8;           // gate (0..3), constant per block
    const int ub = (gbase & 255) + tx * 8;  // unit base for this thread
#pragma unroll
    for (int i = 0; i < 8; ++i) {
        int v = vbase + ty * 8 + i;
        if (v < VSZ) {
#pragma unroll
            for (int j = 0; j < 8; ++j) {
                int g = gbase + tx * 8 + j;
                g_pre[dir][v][(ub + j) * 4 + q] = acc[i][j] + bias[g];
            }
        }
    }
}

// ---------------- barrier state init ----------------
__global__ void barrier_init_kernel() { g_count = 0u; g_sense = 0u; }

// ---------------- Kernel 2: persistent biLSTM (R12 winner; float4 pre-gather) ----------------
__device__ __forceinline__ float sigf(float x) { return 1.f / (1.f + __expf(-x)); }

// Global CG-style grid barrier (R12 winner): fence only in elected thread.
__device__ __forceinline__ void grid_barrier(int tid, unsigned target) {
    __syncthreads();               // all threads' h stores happen-before tid0's fence
    if (tid == 0) {
        __threadfence();           // publish (cumulative over the block)
        unsigned arr = atomicAdd(&g_count, 1u);
        if (arr == NCTA_LSTM - 1u) {
            atomicExch(&g_count, 0u);
            __threadfence();
            atomicExch(&g_sense, target);
        } else {
            while (*(volatile unsigned*)&g_sense < target) { }
        }
    }
    __syncthreads();
}

__global__ void __launch_bounds__(256) lstm_kernel(
    const int* __restrict__ x,
    const float* __restrict__ whh_f, const float* __restrict__ whh_b)
{
    extern __shared__ float sm[];
    float* wsm = sm;          // [256][16] : wsm[k*16 + u*4 + q]
    float* hsm = sm + 4096;   // [256][64] : hsm[k*64 + b]

    const int tid = threadIdx.x;
    const int bx  = blockIdx.x;
    const int dir = bx >> 6;
    const int u0  = (bx & 63) * 4;
    const int ul  = tid >> 6;
    const int b   = tid & 63;

    const float* __restrict__ whh = dir ? whh_b : whh_f;

    for (int i = tid; i < 4096; i += 256) {
        int r = i >> 8, k = i & 255;
        int u = r >> 2, qq = r & 3;
        wsm[k * 16 + u * 4 + qq] = whh[(size_t)(qq * 256 + u0 + u) * 256 + k];
    }
    g_hbuf[dir][0][u0 + ul][b] = 0.f;

    grid_barrier(tid, 1u);

    float c = 0.f;
    const float* __restrict__ preb = &g_pre[dir][0][0];

    for (int t = 0; t < TT; ++t) {
        const int tpos = dir ? (TT - 1 - t) : t;
        const int tok = __ldg(&x[b * TT + tpos]);
        // single float4 gather: gates (i,f,g,o) for unit u0+ul of this token
        float4 pv = __ldg((const float4*)(preb + (size_t)tok * G4) + (u0 + ul));
        float a0 = pv.x, a1 = pv.y, a2 = pv.z, a3 = pv.w;

        // h-fill: L1-bypass loads (coherent without per-thread fences)
        const float4* hg = (const float4*)&g_hbuf[dir][t & 1][0][0];
        float4* hs4 = (float4*)hsm;
#pragma unroll
        for (int i = 0; i < 16; ++i) hs4[i * 256 + tid] = __ldcg(&hg[i * 256 + tid]);
        __syncthreads();

#pragma unroll 8
        for (int k = 0; k < 256; ++k) {
            float4 w = *(const float4*)&wsm[k * 16 + ul * 4];
            float hv = hsm[k * 64 + b];
            a0 = fmaf(w.x, hv, a0);
            a1 = fmaf(w.y, hv, a1);
            a2 = fmaf(w.z, hv, a2);
            a3 = fmaf(w.w, hv, a3);
        }

        float ig = sigf(a0), fg = sigf(a1), gg = tanhf(a2), og = sigf(a3);
        c = fg * c + ig * gg;
        float h = og * tanhf(c);

        g_hbuf[dir][(t + 1) & 1][u0 + ul][b] = h;
        g_hall[dir][tpos][u0 + ul][b] = h;

        grid_barrier(tid, (unsigned)(t + 2));  // also protects hsm reuse
    }
}

// ---------------- Kernel 3: emissions (proven, 54us) ----------------
__global__ void __launch_bounds__(384) emission_kernel(
    const float* __restrict__ wc, const float* __restrict__ bc)
{
    extern __shared__ float wcs[];   // [512][24]

    const int t = blockIdx.x;
    const int tid = threadIdx.x;

    for (int i = tid; i < KP * 512; i += 384) {
        int k = i / 512, u = i - k * 512;
        wcs[u * KP + k] = (k < KT) ? wc[k * 512 + u] : 0.f;
    }
    __syncthreads();

    const int kk = tid >> 6;   // 0..5
    const int b  = tid & 63;

    float r0 = 0.f, r1 = 0.f, r2 = 0.f, r3 = 0.f;
    const float* h0 = &g_hall[0][t][0][0] + b;
    const float* h1 = &g_hall[1][t][0][0] + b;
#pragma unroll 8
    for (int u = 0; u < 256; ++u) {
        float4 w = *(const float4*)&wcs[u * KP + kk * 4];
        float hv = __ldcg(h0 + u * 64);
        r0 = fmaf(w.x, hv, r0);
        r1 = fmaf(w.y, hv, r1);
        r2 = fmaf(w.z, hv, r2);
        r3 = fmaf(w.w, hv, r3);
    }
#pragma unroll 8
    for (int u = 0; u < 256; ++u) {
        float4 w = *(const float4*)&wcs[(u + 256) * KP + kk * 4];
        float hv = __ldcg(h1 + u * 64);
        r0 = fmaf(w.x, hv, r0);
        r1 = fmaf(w.y, hv, r1);
        r2 = fmaf(w.z, hv, r2);
        r3 = fmaf(w.w, hv, r3);
    }

    const int k0 = kk * 4;
    float4 o;
    o.x = r0 + __ldg(&bc[min(k0 + 0, KT - 1)]);
    o.y = r1 + __ldg(&bc[min(k0 + 1, KT - 1)]);
    o.z = r2 + __ldg(&bc[min(k0 + 2, KT - 1)]);
    o.w = r3 + __ldg(&bc[min(k0 + 3, KT - 1)]);
    *(float4*)&g_em[t][b][k0] = o;
}

// ---------------- Kernel 4: CRF — warp0 viterbi, warp1 forward (proven) ----------------
__global__ void __launch_bounds__(64) crf_kernel(
    const int* __restrict__ y,
    const float* __restrict__ startv, const float* __restrict__ endv,
    const float* __restrict__ trans, float* __restrict__ out)
{
    __shared__ float tr[KT * KT];
    __shared__ float sv[32];
    __shared__ float sa[32];
    __shared__ unsigned char bp[TT][KT];

    const int b = blockIdx.x;
    const int tid = threadIdx.x;
    const int w = tid >> 5;
    const int lane = tid & 31;
    const bool act = lane < KT;

    for (int i = tid; i < KT * KT; i += 64) tr[i] = trans[i];
    __syncthreads();

    if (w == 0) {
        if (act) sv[lane] = startv[lane] + g_em[0][b][lane];
        __syncwarp();
        float e_next = act ? g_em[1][b][lane] : 0.f;
        for (int t = 1; t < TT; ++t) {
            float e = e_next;
            if (t + 1 < TT) e_next = act ? g_em[t + 1][b][lane] : 0.f;
            float best = -1e30f; int bi = 0;
#pragma unroll
            for (int i = 0; i < KT; ++i) {
                float v = sv[i] + tr[i * KT + lane];
                if (v > best) { best = v; bi = i; }
            }
            __syncwarp();
            if (act) { sv[lane] = best + e; bp[t][lane] = (unsigned char)bi; }
            __syncwarp();
        }
        float fin = act ? sv[lane] + endv[lane] : -1e30f;
        int idx = act ? lane : 0;
#pragma unroll
        for (int o = 16; o; o >>= 1) {
            float of = __shfl_down_sync(0xFFFFFFFFu, fin, o);
            int   oi = __shfl_down_sync(0xFFFFFFFFu, idx, o);
            if (of > fin) { fin = of; idx = oi; }
        }
        idx = __shfl_sync(0xFFFFFFFFu, idx, 0);
        if (lane == 0) {
            int tag = idx;
            out[b * TT + TT - 1] = (float)tag;
            for (int t = TT - 1; t >= 1; --t) {
                tag = bp[t][tag];
                out[b * TT + t - 1] = (float)tag;
            }
        }
    } else {
        if (act) sa[lane] = startv[lane] + g_em[0][b][lane];
        __syncwarp();
        float e_next = act ? g_em[1][b][lane] : 0.f;
        for (int t = 1; t < TT; ++t) {
            float e = e_next;
            if (t + 1 < TT) e_next = act ? g_em[t + 1][b][lane] : 0.f;
            float amax = -1e30f;
#pragma unroll
            for (int i = 0; i < KT; ++i)
                amax = fmaxf(amax, sa[i] + tr[i * KT + lane]);
            float s = 0.f;
#pragma unroll
            for (int i = 0; i < KT; ++i)
                s += __expf(sa[i] + tr[i * KT + lane] - amax);
            float na = amax + __logf(s) + e;
            __syncwarp();
            if (act) sa[lane] = na;
            __syncwarp();
        }
        float fin = act ? sa[lane] + endv[lane] : -1e30f;
        float m = fin;
#pragma unroll
        for (int o = 16; o; o >>= 1) m = fmaxf(m, __shfl_xor_sync(0xFFFFFFFFu, m, o));
        float s = act ? __expf(fin - m) : 0.f;
#pragma unroll
        for (int o = 16; o; o >>= 1) s += __shfl_xor_sync(0xFFFFFFFFu, s, o);
        float z = m + __logf(s);

        float part = 0.f;
        for (int t = 1 + lane; t < TT; t += 32) {
            int yp = y[b * TT + t - 1], yc = y[b * TT + t];
            part += tr[yp * KT + yc] + g_em[t][b][yc];
        }
#pragma unroll
        for (int o = 16; o; o >>= 1) part += __shfl_down_sync(0xFFFFFFFFu, part, o);
        if (lane == 0) {
            int y0 = y[b * TT];
            int yl = y[b * TT + TT - 1];
            float num = startv[y0] + g_em[0][b][y0] + part + endv[yl];
            g_nll[b] = num - z;
        }
    }
}

// ---------------- Kernel 5: finalize loss ----------------
__global__ void __launch_bounds__(64) finalize_kernel(float* out, int out_size)
{
    __shared__ float s[64];
    s[threadIdx.x] = g_nll[threadIdx.x];
    __syncthreads();
    if (threadIdx.x == 0) {
        float t = 0.f;
        for (int i = 0; i < 64; ++i) t += s[i];
        float loss = t / 64.f;
        if (out_size > BT) out[BT] = loss;
        if (out_size - 1 > BT) out[out_size - 1] = loss;
    }
}

// ---------------- launch ----------------
extern "C" void kernel_launch(void* const* d_in, const int* in_sizes, int n_in,
                              void* d_out, int out_size)
{
    const int*   x      = (const int*)d_in[0];
    const int*   y      = (const int*)d_in[1];
    const float* emb    = (const float*)d_in[3];
    const float* wih_f  = (const float*)d_in[4];
    const float* whh_f  = (const float*)d_in[5];
    const float* b_f    = (const float*)d_in[6];
    const float* wih_b  = (const float*)d_in[7];
    const float* whh_b  = (const float*)d_in[8];
    const float* b_b    = (const float*)d_in[9];
    const float* wc     = (const float*)d_in[10];
    const float* bc     = (const float*)d_in[11];
    const float* startv = (const float*)d_in[12];
    const float* endv   = (const float*)d_in[13];
    const float* trans  = (const float*)d_in[14];
    float* out = (float*)d_out;

    cudaFuncSetAttribute(lstm_kernel,
        cudaFuncAttributeMaxDynamicSharedMemorySize, 81920);
    cudaFuncSetAttribute(emission_kernel,
        cudaFuncAttributeMaxDynamicSharedMemorySize, 49152);

    gemm_pre_kernel<<<dim3(8, 166, 2), 256>>>(emb, wih_f, b_f, wih_b, b_b);
    barrier_init_kernel<<<1, 1>>>();
    lstm_kernel<<<NCTA_LSTM, 256, 81920>>>(x, whh_f, whh_b);
    emission_kernel<<<TT, 384, 49152>>>(wc, bc);
    crf_kernel<<<BB, 64>>>(y, startv, endv, trans, out);
    finalize_kernel<<<1, 64>>>(out, out_size);
}

// round 17
// speedup vs baseline: 1.0948x; 1.0564x over previous
#include <cuda_runtime.h>
#include <cuda_bf16.h>
#include <math.h>

#define VSZ 21128
#define HSZ 256
#define KT  21
#define KP  24
#define BB  64
#define TT  512
#define G4  1024
#define NCTA_LSTM 128u
#define BT  (BB*TT)

// ---------------- device scratch ----------------
__device__ float g_pre[2][VSZ][G4];          // emb@wih^T + b per dir
__device__ float g_hbuf[2][2][HSZ][BB];      // [dir][parity][unit][batch]
__device__ float g_hall[2][TT][HSZ][BB];     // [dir][t][unit][batch]
__device__ float g_em[TT][BB][KP];           // emissions [t][b][k] (padded 24)
__device__ float g_nll[BB];
__device__ unsigned g_count;

// ---------------- Kernel 1: vocab pre-projection GEMM (double-buffered, proven) ----------------
__global__ void __launch_bounds__(256) gemm_pre_kernel(
    const float* __restrict__ emb,
    const float* __restrict__ wih_f, const float* __restrict__ b_f,
    const float* __restrict__ wih_b, const float* __restrict__ b_b)
{
    __shared__ float As[2][16][128];
    __shared__ float Bs[2][16][128];

    const int dir = blockIdx.z;
    const float* __restrict__ W    = dir ? wih_b : wih_f;
    const float* __restrict__ bias = dir ? b_b   : b_f;
    const int vbase = blockIdx.y * 128;
    const int gbase = blockIdx.x * 128;
    const int tid = threadIdx.x;
    const int tx = tid & 15;
    const int ty = tid >> 4;

    int rowj[2], c4j[2], vj[2], gj[2];
#pragma unroll
    for (int j = 0; j < 2; ++j) {
        int f = tid * 2 + j;
        rowj[j] = f >> 2;
        c4j[j]  = f & 3;
        int v = vbase + rowj[j]; if (v >= VSZ) v = VSZ - 1;
        vj[j] = v;
        gj[j] = gbase + rowj[j];
    }

    float acc[8][8];
#pragma unroll
    for (int i = 0; i < 8; ++i)
#pragma unroll
        for (int j = 0; j < 8; ++j) acc[i][j] = 0.f;

    float4 ar[2], br[2];

#pragma unroll
    for (int j = 0; j < 2; ++j) {
        ar[j] = *(const float4*)&emb[(size_t)vj[j] * 256 + c4j[j] * 4];
        br[j] = *(const float4*)&W[(size_t)gj[j] * 256 + c4j[j] * 4];
    }
#pragma unroll
    for (int j = 0; j < 2; ++j) {
        int r = rowj[j], c4 = c4j[j];
        As[0][c4*4+0][r] = ar[j].x; As[0][c4*4+1][r] = ar[j].y;
        As[0][c4*4+2][r] = ar[j].z; As[0][c4*4+3][r] = ar[j].w;
        Bs[0][c4*4+0][r] = br[j].x; Bs[0][c4*4+1][r] = br[j].y;
        Bs[0][c4*4+2][r] = br[j].z; Bs[0][c4*4+3][r] = br[j].w;
    }
    __syncthreads();

    for (int c = 0; c < 16; ++c) {
        const int buf = c & 1;
        if (c < 15) {
            const int k0 = (c + 1) * 16;
#pragma unroll
            for (int j = 0; j < 2; ++j) {
                ar[j] = *(const float4*)&emb[(size_t)vj[j] * 256 + k0 + c4j[j] * 4];
                br[j] = *(const float4*)&W[(size_t)gj[j] * 256 + k0 + c4j[j] * 4];
            }
        }
#pragma unroll
        for (int k = 0; k < 16; ++k) {
            float4 a0 = *(const float4*)&As[buf][k][ty*8];
            float4 a1 = *(const float4*)&As[buf][k][ty*8+4];
            float4 c0 = *(const float4*)&Bs[buf][k][tx*8];
            float4 c1 = *(const float4*)&Bs[buf][k][tx*8+4];
            float am[8] = {a0.x,a0.y,a0.z,a0.w,a1.x,a1.y,a1.z,a1.w};
            float bm[8] = {c0.x,c0.y,c0.z,c0.w,c1.x,c1.y,c1.z,c1.w};
#pragma unroll
            for (int i = 0; i < 8; ++i)
#pragma unroll
                for (int j = 0; j < 8; ++j)
                    acc[i][j] = fmaf(am[i], bm[j], acc[i][j]);
        }
        if (c < 15) {
            __syncthreads();
            const int nb = (c + 1) & 1;
#pragma unroll
            for (int j = 0; j < 2; ++j) {
                int r = rowj[j], c4 = c4j[j];
                As[nb][c4*4+0][r] = ar[j].x; As[nb][c4*4+1][r] = ar[j].y;
                As[nb][c4*4+2][r] = ar[j].z; As[nb][c4*4+3][r] = ar[j].w;
                Bs[nb][c4*4+0][r] = br[j].x; Bs[nb][c4*4+1][r] = br[j].y;
                Bs[nb][c4*4+2][r] = br[j].z; Bs[nb][c4*4+3][r] = br[j].w;
            }
            __syncthreads();
        }
    }

#pragma unroll
    for (int i = 0; i < 8; ++i) {
        int v = vbase + ty * 8 + i;
        if (v < VSZ) {
#pragma unroll
            for (int j = 0; j < 8; j += 4) {
                int g = gbase + tx * 8 + j;
                float4 o;
                o.x = acc[i][j+0] + bias[g+0];
                o.y = acc[i][j+1] + bias[g+1];
                o.z = acc[i][j+2] + bias[g+2];
                o.w = acc[i][j+3] + bias[g+3];
                *(float4*)&g_pre[dir][v][g] = o;
            }
        }
    }
}

// ---------------- barrier state init ----------------
__global__ void barrier_init_kernel() { g_count = 0u; }

// ---------------- Kernel 2: persistent biLSTM (R12 winner + count-poll barrier) ----------------
__device__ __forceinline__ float sigf(float x) { return 1.f / (1.f + __expf(-x)); }

// Monotonic count-poll barrier: last arrival's add IS the release.
// Each CTA's threadfence precedes its add; observing the full sum implies all
// fences (cumulativity) -> all h stores visible at L2 (reads use __ldcg).
__device__ __forceinline__ void grid_barrier(int tid, unsigned round) {
    __syncthreads();               // all threads' h stores happen-before tid0's fence
    if (tid == 0) {
        __threadfence();           // publish (cumulative over the block)
        atomicAdd(&g_count, 1u);
        const unsigned want = round * NCTA_LSTM;
        while (*(volatile unsigned*)&g_count < want) { }
    }
    __syncthreads();
}

__global__ void __launch_bounds__(256) lstm_kernel(
    const int* __restrict__ x,
    const float* __restrict__ whh_f, const float* __restrict__ whh_b)
{
    extern __shared__ float sm[];
    float* wsm = sm;          // [256][16] : wsm[k*16 + u*4 + q]
    float* hsm = sm + 4096;   // [256][64] : hsm[k*64 + b]

    const int tid = threadIdx.x;
    const int bx  = blockIdx.x;
    const int dir = bx >> 6;
    const int u0  = (bx & 63) * 4;
    const int ul  = tid >> 6;
    const int b   = tid & 63;

    const float* __restrict__ whh = dir ? whh_b : whh_f;

    for (int i = tid; i < 4096; i += 256) {
        int r = i >> 8, k = i & 255;
        int u = r >> 2, q = r & 3;
        wsm[k * 16 + u * 4 + q] = whh[(size_t)(q * 256 + u0 + u) * 256 + k];
    }
    g_hbuf[dir][0][u0 + ul][b] = 0.f;

    grid_barrier(tid, 1u);

    float c = 0.f;
    const float* __restrict__ preb = &g_pre[dir][0][0];

    for (int t = 0; t < TT; ++t) {
        const int tpos = dir ? (TT - 1 - t) : t;
        const int tok = __ldg(&x[b * TT + tpos]);
        const float* pr = preb + (size_t)tok * G4;
        float a0 = pr[      u0 + ul];
        float a1 = pr[256 + u0 + ul];
        float a2 = pr[512 + u0 + ul];
        float a3 = pr[768 + u0 + ul];

        // h-fill: L1-bypass loads (coherent with the fence/add protocol)
        const float4* hg = (const float4*)&g_hbuf[dir][t & 1][0][0];
        float4* hs4 = (float4*)hsm;
#pragma unroll
        for (int i = 0; i < 16; ++i) hs4[i * 256 + tid] = __ldcg(&hg[i * 256 + tid]);
        __syncthreads();

#pragma unroll 8
        for (int k = 0; k < 256; ++k) {
            float4 w = *(const float4*)&wsm[k * 16 + ul * 4];
            float hv = hsm[k * 64 + b];
            a0 = fmaf(w.x, hv, a0);
            a1 = fmaf(w.y, hv, a1);
            a2 = fmaf(w.z, hv, a2);
            a3 = fmaf(w.w, hv, a3);
        }

        float ig = sigf(a0), fg = sigf(a1), gg = tanhf(a2), og = sigf(a3);
        c = fg * c + ig * gg;
        float h = og * tanhf(c);

        g_hbuf[dir][(t + 1) & 1][u0 + ul][b] = h;
        g_hall[dir][tpos][u0 + ul][b] = h;

        grid_barrier(tid, (unsigned)(t + 2));  // also protects hsm reuse
    }
}

// ---------------- Kernel 3: emissions (proven, 54us) ----------------
__global__ void __launch_bounds__(384) emission_kernel(
    const float* __restrict__ wc, const float* __restrict__ bc)
{
    extern __shared__ float wcs[];   // [512][24]

    const int t = blockIdx.x;
    const int tid = threadIdx.x;

    for (int i = tid; i < KP * 512; i += 384) {
        int k = i / 512, u = i - k * 512;
        wcs[u * KP + k] = (k < KT) ? wc[k * 512 + u] : 0.f;
    }
    __syncthreads();

    const int kk = tid >> 6;   // 0..5
    const int b  = tid & 63;

    float r0 = 0.f, r1 = 0.f, r2 = 0.f, r3 = 0.f;
    const float* h0 = &g_hall[0][t][0][0] + b;
    const float* h1 = &g_hall[1][t][0][0] + b;
#pragma unroll 8
    for (int u = 0; u < 256; ++u) {
        float4 w = *(const float4*)&wcs[u * KP + kk * 4];
        float hv = __ldcg(h0 + u * 64);
        r0 = fmaf(w.x, hv, r0);
        r1 = fmaf(w.y, hv, r1);
        r2 = fmaf(w.z, hv, r2);
        r3 = fmaf(w.w, hv, r3);
    }
#pragma unroll 8
    for (int u = 0; u < 256; ++u) {
        float4 w = *(const float4*)&wcs[(u + 256) * KP + kk * 4];
        float hv = __ldcg(h1 + u * 64);
        r0 = fmaf(w.x, hv, r0);
        r1 = fmaf(w.y, hv, r1);
        r2 = fmaf(w.z, hv, r2);
        r3 = fmaf(w.w, hv, r3);
    }

    const int k0 = kk * 4;
    float4 o;
    o.x = r0 + __ldg(&bc[min(k0 + 0, KT - 1)]);
    o.y = r1 + __ldg(&bc[min(k0 + 1, KT - 1)]);
    o.z = r2 + __ldg(&bc[min(k0 + 2, KT - 1)]);
    o.w = r3 + __ldg(&bc[min(k0 + 3, KT - 1)]);
    *(float4*)&g_em[t][b][k0] = o;
}

// ---------------- Kernel 4: CRF — warp0 viterbi, warp1 forward (proven) ----------------
__global__ void __launch_bounds__(64) crf_kernel(
    const int* __restrict__ y,
    const float* __restrict__ startv, const float* __restrict__ endv,
    const float* __restrict__ trans, float* __restrict__ out)
{
    __shared__ float tr[KT * KT];
    __shared__ float sv[32];
    __shared__ float sa[32];
    __shared__ unsigned char bp[TT][KT];

    const int b = blockIdx.x;
    const int tid = threadIdx.x;
    const int w = tid >> 5;
    const int lane = tid & 31;
    const bool act = lane < KT;

    for (int i = tid; i < KT * KT; i += 64) tr[i] = trans[i];
    __syncthreads();

    if (w == 0) {
        if (act) sv[lane] = startv[lane] + g_em[0][b][lane];
        __syncwarp();
        float e_next = act ? g_em[1][b][lane] : 0.f;
        for (int t = 1; t < TT; ++t) {
            float e = e_next;
            if (t + 1 < TT) e_next = act ? g_em[t + 1][b][lane] : 0.f;
            float best = -1e30f; int bi = 0;
#pragma unroll
            for (int i = 0; i < KT; ++i) {
                float v = sv[i] + tr[i * KT + lane];
                if (v > best) { best = v; bi = i; }
            }
            __syncwarp();
            if (act) { sv[lane] = best + e; bp[t][lane] = (unsigned char)bi; }
            __syncwarp();
        }
        float fin = act ? sv[lane] + endv[lane] : -1e30f;
        int idx = act ? lane : 0;
#pragma unroll
        for (int o = 16; o; o >>= 1) {
            float of = __shfl_down_sync(0xFFFFFFFFu, fin, o);
            int   oi = __shfl_down_sync(0xFFFFFFFFu, idx, o);
            if (of > fin) { fin = of; idx = oi; }
        }
        idx = __shfl_sync(0xFFFFFFFFu, idx, 0);
        if (lane == 0) {
            int tag = idx;
            out[b * TT + TT - 1] = (float)tag;
            for (int t = TT - 1; t >= 1; --t) {
                tag = bp[t][tag];
                out[b * TT + t - 1] = (float)tag;
            }
        }
    } else {
        if (act) sa[lane] = startv[lane] + g_em[0][b][lane];
        __syncwarp();
        float e_next = act ? g_em[1][b][lane] : 0.f;
        for (int t = 1; t < TT; ++t) {
            float e = e_next;
            if (t + 1 < TT) e_next = act ? g_em[t + 1][b][lane] : 0.f;
            float amax = -1e30f;
#pragma unroll
            for (int i = 0; i < KT; ++i)
                amax = fmaxf(amax, sa[i] + tr[i * KT + lane]);
            float s = 0.f;
#pragma unroll
            for (int i = 0; i < KT; ++i)
                s += __expf(sa[i] + tr[i * KT + lane] - amax);
            float na = amax + __logf(s) + e;
            __syncwarp();
            if (act) sa[lane] = na;
            __syncwarp();
        }
        float fin = act ? sa[lane] + endv[lane] : -1e30f;
        float m = fin;
#pragma unroll
        for (int o = 16; o; o >>= 1) m = fmaxf(m, __shfl_xor_sync(0xFFFFFFFFu, m, o));
        float s = act ? __expf(fin - m) : 0.f;
#pragma unroll
        for (int o = 16; o; o >>= 1) s += __shfl_xor_sync(0xFFFFFFFFu, s, o);
        float z = m + __logf(s);

        float part = 0.f;
        for (int t = 1 + lane; t < TT; t += 32) {
            int yp = y[b * TT + t - 1], yc = y[b * TT + t];
            part += tr[yp * KT + yc] + g_em[t][b][yc];
        }
#pragma unroll
        for (int o = 16; o; o >>= 1) part += __shfl_down_sync(0xFFFFFFFFu, part, o);
        if (lane == 0) {
            int y0 = y[b * TT];
            int yl = y[b * TT + TT - 1];
            float num = startv[y0] + g_em[0][b][y0] + part + endv[yl];
            g_nll[b] = num - z;
        }
    }
}

// ---------------- Kernel 5: finalize loss ----------------
__global__ void __launch_bounds__(64) finalize_kernel(float* out, int out_size)
{
    __shared__ float s[64];
    s[threadIdx.x] = g_nll[threadIdx.x];
    __syncthreads();
    if (threadIdx.x == 0) {
        float t = 0.f;
        for (int i = 0; i < 64; ++i) t += s[i];
        float loss = t / 64.f;
        if (out_size > BT) out[BT] = loss;
        if (out_size - 1 > BT) out[out_size - 1] = loss;
    }
}

// ---------------- launch ----------------
extern "C" void kernel_launch(void* const* d_in, const int* in_sizes, int n_in,
                              void* d_out, int out_size)
{
    const int*   x      = (const int*)d_in[0];
    const int*   y      = (const int*)d_in[1];
    const float* emb    = (const float*)d_in[3];
    const float* wih_f  = (const float*)d_in[4];
    const float* whh_f  = (const float*)d_in[5];
    const float* b_f    = (const float*)d_in[6];
    const float* wih_b  = (const float*)d_in[7];
    const float* whh_b  = (const float*)d_in[8];
    const float* b_b    = (const float*)d_in[9];
    const float* wc     = (const float*)d_in[10];
    const float* bc     = (const float*)d_in[11];
    const float* startv = (const float*)d_in[12];
    const float* endv   = (const float*)d_in[13];
    const float* trans  = (const float*)d_in[14];
    float* out = (float*)d_out;

    cudaFuncSetAttribute(lstm_kernel,
        cudaFuncAttributeMaxDynamicSharedMemorySize, 81920);
    cudaFuncSetAttribute(emission_kernel,
        cudaFuncAttributeMaxDynamicSharedMemorySize, 49152);

    gemm_pre_kernel<<<dim3(8, 166, 2), 256>>>(emb, wih_f, b_f, wih_b, b_b);
    barrier_init_kernel<<<1, 1>>>();
    lstm_kernel<<<NCTA_LSTM, 256, 81920>>>(x, whh_f, whh_b);
    emission_kernel<<<TT, 384, 49152>>>(wc, bc);
    crf_kernel<<<BB, 64>>>(y, startv, endv, trans, out);
    finalize_kernel<<<1, 64>>>(out, out_size);
}